// round 9
// baseline (speedup 1.0000x reference)
#include <cuda_runtime.h>
#include <cstdint>

// HH_Synaptic, Round 9: gate updates are affine in state: x' = c1(V)*x + c0(V).
// Tabulate (c0,c1)+deltas for m,n,h gates in shared memory (4096 bins over
// V in [-128,64], 48B/bin = 192KB dynamic smem, linear interp). Per step this
// removes 4 ex2 + 2 rcp + ~35 instrs from the dependency spine.
// V-update, y-gate (series rcp), and output sigmoid unchanged from R8.

#define N_DIM 2000
#define L_DIM 1024
#define PF    4
#define BINS  4096
#define VLO   (-128.0f)
#define VRANGE 192.0f
#define DELTA (VRANGE / BINS)            // 0.046875
#define INVD  (BINS / VRANGE)            // 21.333...
#define TAB_BYTES (BINS * 48)

__device__ __forceinline__ float ex2f_(float x){ float r; asm("ex2.approx.f32 %0, %1;" : "=f"(r) : "f"(x)); return r; }
__device__ __forceinline__ float rcpf_(float x){ float r; asm("rcp.approx.f32 %0, %1;" : "=f"(r) : "f"(x)); return r; }

// accurate rate constants at a table node (build-time only)
__device__ void node_coeffs(float V, float* c) {
    // c = {cn0, cn1, cm0, cm1, ch0, ch1}
    float dv25 = V - 25.0f, dv35 = V + 35.0f;
    float aN, bN, aM, bM;
    if (dv25 == 0.0f) { aN = 0.18f;  bN = 0.018f; }   // analytic limits (smooth table)
    else {
        aN =  0.02f  * dv25 / (1.0f - expf(-dv25 / 9.0f));
        bN = -0.002f * dv25 / (1.0f - expf( dv25 / 9.0f));
    }
    if (dv35 == 0.0f) { aM = 1.638f; bM = 1.116f; }
    else {
        aM =  0.182f * dv35 / (1.0f - expf(-dv35 / 9.0f));
        bM = -0.124f * dv35 / (1.0f - expf( dv35 / 9.0f));
    }
    float aH = 0.25f * expf((-V - 90.0f) / 12.0f);
    float bH = 0.25f * expf(( V + 34.0f) / 12.0f);

    float pN = 0.01f * (aN + bN);
    float pM = 0.01f * (aM + bM);
    float pH = 0.01f * (aH + bH);
    c[0] = 0.02f * aN / (1.0f + pN);  c[1] = (1.0f - pN) / (1.0f + pN);
    c[2] = 0.02f * aM / (1.0f + pM);  c[3] = (1.0f - pM) / (1.0f + pM);
    c[4] = 0.02f * aH / (1.0f + pH);  c[5] = (1.0f - pH) / (1.0f + pH);
}

__global__ __launch_bounds__(128, 1)
void hh_synaptic_kernel(const float* __restrict__ z, float* __restrict__ out) {
    extern __shared__ float4 tab[];    // tab[i*3+0]={cn0,cn1,cm0,cm1} tab[i*3+1]=deltas tab[i*3+2]={ch0,ch1,dh0,dh1}

    // ---- build LUT (one-time, ~32 bins/thread) ----
    for (int i = threadIdx.x; i < BINS; i += blockDim.x) {
        float c0[6], c1[6];
        float Vn0 = VLO + (float)i * DELTA;
        node_coeffs(Vn0, c0);
        node_coeffs(Vn0 + DELTA, c1);
        float4 A, D, H;
        A.x = c0[0]; A.y = c0[1]; A.z = c0[2]; A.w = c0[3];
        D.x = c1[0] - c0[0]; D.y = c1[1] - c0[1]; D.z = c1[2] - c0[2]; D.w = c1[3] - c0[3];
        H.x = c0[4]; H.y = c0[5]; H.z = c1[4] - c0[4]; H.w = c1[5] - c0[5];
        tab[i * 3 + 0] = A;
        tab[i * 3 + 1] = D;
        tab[i * 3 + 2] = H;
    }
    __syncthreads();

    const int idx = blockIdx.x * blockDim.x + threadIdx.x;   // 0 .. 16383
    const int b = idx >> 10;
    const int l = idx & (L_DIM - 1);

    const float* zp = z   + (size_t)b * (N_DIM * L_DIM) + l;
    float*       op = out + (size_t)b * (N_DIM * L_DIM) + l;

    const float LOG2E = 1.4426950408889634f;
    const float cSIG  = LOG2E / 3.0f;

    // Reference's exact-equality patch constants (V==25 -> n gate, V==-35 -> m gate)
    const float pN_ = 0.01f*(0.18f+0.08f),  pM_ = 0.01f*(1.638f+1.16f);
    const float kNp = (1.0f-pN_)/(1.0f+pN_), cNp = (0.02f*0.18f)/(1.0f+pN_);
    const float kMp = (1.0f-pM_)/(1.0f+pM_), cMp = (0.02f*1.638f)/(1.0f+pM_);

    // State
    float V = -70.0f;
    float m = 0.0f, n = 0.0f, h = 1.0f, y = 0.0f;

    // k = 0 output
    {
        float e = ex2f_(-(V + 20.0f) * cSIG);
        op[0] = rcpf_(1.0f + e);
    }

    // z prefetch ring: step k consumes z index (k-1)
    float zbuf[PF];
    #pragma unroll
    for (int j = 0; j < PF; ++j)
        zbuf[j] = __ldg(zp + (size_t)j * L_DIM);

    float* ol = op + L_DIM;

    #pragma unroll 4
    for (int k = 1; k < N_DIM; ++k) {
        float zc = zbuf[0];
        #pragma unroll
        for (int j = 0; j < PF - 1; ++j) zbuf[j] = zbuf[j + 1];
        int pidx = min(k - 1 + PF, N_DIM - 1);
        zbuf[PF - 1] = __ldg(zp + (size_t)pidx * L_DIM);

        // ---- y update (independent of V path): series rcp, pY <= 0.011 ----
        float pY = fmaf(0.01f, zc, 0.001f);
        float rY = fmaf(pY, fmaf(pY, 1.0f - pY, -1.0f), 1.0f);   // 1 - p + p^2 - p^3
        float yn = fmaf(zc, 0.02f, fmaf(-pY, y, y)) * rY;

        // ---- implicit V update (exact) ----
        float mm   = m * m;
        float pow1 = (mm * m) * (40.0f * h);             // GNA*m^3*h
        float n2   = n * n;
        float pow2 = 35.0f * (n2 * n2);                  // GK*n^4
        float G    = 0.01f * ((pow1 + pow2) + (0.3f + y));
        float E    = fmaf(pow1, 55.0f, fmaf(pow2, -77.0f, -19.5f));
        float base = fmaf(0.02f, E, V + 0.02f);          // V + DT*(E+IAPP)
        float r    = rcpf_(1.0f + G);
        float num  = fmaf(-V, G, base);
        float numi = num * INVD;                         // parallel with rcp
        float Vn   = num * r;
        // t = (Vn - VLO) * INVD, built off num*r to keep spine short
        float t    = fmaf(numi, r, -VLO * INVD);
        t = fminf(fmaxf(t, 0.5f), (float)BINS - 1.5f);

        // float-trick nearest-int split (no F2I/I2F latency)
        float s    = t + 8388608.0f;                     // 2^23
        float fl   = s - 8388608.0f;                     // round-to-nearest(t)
        float frac = t - fl;                             // in [-0.5, 0.5]
        uint32_t bi = __float_as_uint(s) & 0x7FFFFFu;    // integer bin

        const float4* bp = &tab[bi * 3];
        float4 A  = bp[0];
        float4 Dl = bp[1];
        float4 Hc = bp[2];

        float cn0 = fmaf(frac, Dl.x, A.x);
        float cn1 = fmaf(frac, Dl.y, A.y);
        float cm0 = fmaf(frac, Dl.z, A.z);
        float cm1 = fmaf(frac, Dl.w, A.w);
        float ch0 = fmaf(frac, Hc.z, Hc.x);
        float ch1 = fmaf(frac, Hc.w, Hc.y);

        // reference's exact-equality singularity patches
        bool sN = (Vn == 25.0f);
        bool sM = (Vn == -35.0f);
        cn0 = sN ? cNp : cn0;  cn1 = sN ? kNp : cn1;
        cm0 = sM ? cMp : cm0;  cm1 = sM ? kMp : cm1;

        // ---- affine gate updates ----
        n = fmaf(cn1, n, cn0);
        m = fmaf(cm1, m, cm0);
        h = fmaf(ch1, h, ch0);
        y = yn;
        V = Vn;

        // ---- output sigmoid (off the recurrence) ----
        float e = ex2f_(fmaf(Vn, -cSIG, -20.0f * cSIG));
        *ol = rcpf_(1.0f + e);
        ol += L_DIM;
    }
}

extern "C" void kernel_launch(void* const* d_in, const int* in_sizes, int n_in,
                              void* d_out, int out_size) {
    const float* z = (const float*)d_in[0];
    float* out = (float*)d_out;
    cudaFuncSetAttribute(hh_synaptic_kernel,
                         cudaFuncAttributeMaxDynamicSharedMemorySize, TAB_BYTES);
    hh_synaptic_kernel<<<128, 128, TAB_BYTES>>>(z, out);
}

// round 10
// speedup vs baseline: 1.0879x; 1.0879x over previous
#include <cuda_runtime.h>

// HH_Synaptic, Round 10: spine surgery on the scalar fused-gate kernel.
// - G' = 1+G accumulated directly (yG staged off-spine from previous step)
// - ex2 args as fma(num*c, r, const): muls overlap the V-update rcp
// - independent ex2 per rail (no shared-exp serialization)
// - h40, yG staged in the previous step's stall shadow

#define N_DIM 2000
#define L_DIM 1024
#define PF    4

__device__ __forceinline__ float ex2f_(float x){ float r; asm("ex2.approx.f32 %0, %1;" : "=f"(r) : "f"(x)); return r; }
__device__ __forceinline__ float rcpf_(float x){ float r; asm("rcp.approx.f32 %0, %1;" : "=f"(r) : "f"(x)); return r; }

__global__ __launch_bounds__(128, 1)
void hh_synaptic_kernel(const float* __restrict__ z, float* __restrict__ out) {
    const int idx = blockIdx.x * blockDim.x + threadIdx.x;   // 0 .. 16383
    const int b = idx >> 10;
    const int l = idx & (L_DIM - 1);

    const float* zp = z   + (size_t)b * (N_DIM * L_DIM) + l;
    float*       op = out + (size_t)b * (N_DIM * L_DIM) + l;

    const float LOG2E = 1.4426950408889634f;
    const float c9    = LOG2E / 9.0f;
    const float c12   = LOG2E / 12.0f;
    const float cSIG  = LOG2E / 3.0f;
    const float cAH01 = 0.01f * 0.25f * expf(-56.0f / 12.0f);  // 0.01*aH coeff

    // Singularity-patch constants (reference's exact-equality cases): x' = k*x + c
    const float pN_ = 0.01f*(0.18f+0.08f),  pM_ = 0.01f*(1.638f+1.16f);
    const float kNp = (1.0f-pN_)/(1.0f+pN_), cNp = (0.02f*0.18f)/(1.0f+pN_);
    const float kMp = (1.0f-pM_)/(1.0f+pM_), cMp = (0.02f*1.638f)/(1.0f+pM_);

    // State
    float V = -70.0f;
    float m = 0.0f, n = 0.0f, h = 1.0f, y = 0.0f;
    // Off-spine staged values
    float yG  = 1.003f;          // 1.003 + 0.01*y
    float h40 = 40.0f;           // 40*h

    // k = 0 output
    {
        float e = ex2f_(-(V + 20.0f) * cSIG);
        op[0] = rcpf_(1.0f + e);
    }

    // z prefetch ring: step k consumes z index (k-1)
    float zbuf[PF];
    #pragma unroll
    for (int j = 0; j < PF; ++j)
        zbuf[j] = __ldg(zp + (size_t)j * L_DIM);

    float* ol = op + L_DIM;

    #pragma unroll 4
    for (int k = 1; k < N_DIM; ++k) {
        float zc = zbuf[0];
        #pragma unroll
        for (int j = 0; j < PF - 1; ++j) zbuf[j] = zbuf[j + 1];
        int pidx = min(k - 1 + PF, N_DIM - 1);
        zbuf[PF - 1] = __ldg(zp + (size_t)pidx * L_DIM);

        // ---- y update (V-independent): series rcp, pY <= 0.011 ----
        float pY = fmaf(0.01f, zc, 0.001f);
        float rY = fmaf(pY, fmaf(pY, 1.0f - pY, -1.0f), 1.0f);   // 1-p+p^2-p^3
        float yn = fmaf(zc, 0.02f, fmaf(-pY, y, y)) * rY;

        // ---- implicit V update: G' = 1+G tracked directly ----
        float mm   = m * m;
        float pow1 = (mm * m) * h40;                     // GNA*m^3*h (h40=40h staged)
        float n2   = n * n;
        float pow2 = 35.0f * (n2 * n2);                  // GK*n^4
        float psum = pow1 + pow2;
        float Gp   = fmaf(0.01f, psum, yG);              // 1 + G  (yG staged)
        float E    = fmaf(pow1, 55.0f, fmaf(pow2, -77.0f, -19.5f));
        float b2   = fmaf(0.02f, E, fmaf(2.0f, V, 0.02f));  // 2V + 0.02E + 0.02
        float r    = rcpf_(Gp);
        float num  = fmaf(-V, Gp, b2);                   // = V(1-G) + DT*(E+IAPP)

        // pre-staged products (overlap the rcp)
        float num9  = num * c9;
        float num12 = num * c12;
        float num01 = num * 0.01f;

        float Vn    = num * r;
        float dv25  = fmaf(num, r, -25.0f);
        float dv35  = fmaf(num, r,  35.0f);
        float dv01N = fmaf(num01, r, -0.25f);            // 0.01*dv25
        float dv01M = fmaf(num01, r,  0.35f);            // 0.01*dv35
        float argN  = fmaf(num9,  r, -25.0f * c9);
        float argM  = fmaf(num9,  r,  35.0f * c9);
        float argHp = fmaf(num12, r,  34.0f * c12);
        float argS  = fmaf(-num * cSIG, r, -20.0f * cSIG);

        float eN  = ex2f_(argN);
        float eM  = ex2f_(argM);
        float eHp = ex2f_(argHp);
        float eHm = ex2f_(-argHp);

        // ---- N rail (fused single-rcp): x' = (sc*dv*e + x*(D-q)) / (D+q) ----
        {
            float D   = eN - 1.0f;
            float set = fmaf(0.02f, eN, 0.002f);
            float q   = dv01N * set;
            float rr  = rcpf_(D + q);
            float scE = (dv25 * eN) * 4.0e-4f;           // 0.02*0.02
            float nm2 = fmaf(n, D - q, scE);
            float res = nm2 * rr;
            n = (dv25 == 0.0f) ? fmaf(n, kNp, cNp) : res;
        }
        // ---- M rail ----
        {
            float D   = eM - 1.0f;
            float set = fmaf(0.182f, eM, 0.124f);
            float q   = dv01M * set;
            float rr  = rcpf_(D + q);
            float scE = (dv35 * eM) * (0.02f * 0.182f);
            float nm2 = fmaf(m, D - q, scE);
            float res = nm2 * rr;
            m = (dv35 == 0.0f) ? fmaf(m, kMp, cMp) : res;
        }
        // ---- h gate ----
        {
            float u  = cAH01  * eHm;                     // 0.01*aH
            float v  = 0.0025f * eHp;                    // 0.01*bH
            float pH = u + v;
            float rr = rcpf_(1.0f + pH);
            float hn = fmaf(2.0f, u, fmaf(-pH, h, h));   // 0.02*aH + (1-pH)h
            h = hn * rr;
        }

        // stage off-spine values for next step
        h40 = 40.0f * h;
        y   = yn;
        yG  = fmaf(0.01f, yn, 1.003f);
        V   = Vn;

        // ---- output sigmoid (off the recurrence) ----
        float e = ex2f_(argS);
        *ol = rcpf_(1.0f + e);
        ol += L_DIM;
    }
}

extern "C" void kernel_launch(void* const* d_in, const int* in_sizes, int n_in,
                              void* d_out, int out_size) {
    const float* z = (const float*)d_in[0];
    float* out = (float*)d_out;
    hh_synaptic_kernel<<<128, 128>>>(z, out);
}

// round 11
// speedup vs baseline: 1.1802x; 1.0849x over previous
#include <cuda_runtime.h>

// HH_Synaptic, Round 11: shadow-filling schedule.
// - output sigmoid+store software-pipelined one step (runs in next step's
//   pow-chain + rcp(Gp) stall shadow)
// - h-rail rescaled by eHp: one ex2 + one rcp (no eHm) -> 8 MUFU/step
// - N/M/H rails interleaved line-by-line; 16-cyc head via (m*m)*(m*h40)

#define N_DIM 2000
#define L_DIM 1024
#define PF    4

__device__ __forceinline__ float ex2f_(float x){ float r; asm("ex2.approx.f32 %0, %1;" : "=f"(r) : "f"(x)); return r; }
__device__ __forceinline__ float rcpf_(float x){ float r; asm("rcp.approx.f32 %0, %1;" : "=f"(r) : "f"(x)); return r; }

__global__ __launch_bounds__(128, 1)
void hh_synaptic_kernel(const float* __restrict__ z, float* __restrict__ out) {
    const int idx = blockIdx.x * blockDim.x + threadIdx.x;   // 0 .. 16383
    const int b = idx >> 10;
    const int l = idx & (L_DIM - 1);

    const float* zp = z   + (size_t)b * (N_DIM * L_DIM) + l;
    float*       op = out + (size_t)b * (N_DIM * L_DIM) + l;

    const float LOG2E = 1.4426950408889634f;
    const float c9    = LOG2E / 9.0f;
    const float c12   = LOG2E / 12.0f;
    const float cSIG  = LOG2E / 3.0f;
    const float cAH01 = 0.01f * 0.25f * expf(-56.0f / 12.0f);  // 0.01*aH*e^{(V+34)/12}

    // Singularity-patch constants (reference's exact-equality cases): x' = k*x + c
    const float pN_ = 0.01f*(0.18f+0.08f),  pM_ = 0.01f*(1.638f+1.16f);
    const float kNp = (1.0f-pN_)/(1.0f+pN_), cNp = (0.02f*0.18f)/(1.0f+pN_);
    const float kMp = (1.0f-pM_)/(1.0f+pM_), cMp = (0.02f*1.638f)/(1.0f+pM_);

    // State
    float V = -70.0f;
    float m = 0.0f, n = 0.0f, h = 1.0f, y = 0.0f;
    float yG  = 1.003f;          // 1.003 + 0.01*y   (staged off-spine)
    float h40 = 40.0f;           // 40*h             (staged off-spine)

    // argS for row 0 (V = -70): output store pipelined into first iteration
    float argS_prev = -(V + 20.0f) * cSIG;
    float* olPrev = op;          // row to store at top of next iteration

    // z prefetch ring: step k consumes z index (k-1)
    float zbuf[PF];
    #pragma unroll
    for (int j = 0; j < PF; ++j)
        zbuf[j] = __ldg(zp + (size_t)j * L_DIM);

    #pragma unroll 4
    for (int k = 1; k < N_DIM; ++k) {
        float zc = zbuf[0];
        #pragma unroll
        for (int j = 0; j < PF - 1; ++j) zbuf[j] = zbuf[j + 1];
        int pidx = min(k - 1 + PF, N_DIM - 1);
        zbuf[PF - 1] = __ldg(zp + (size_t)pidx * L_DIM);

        // ---- head: 16-cyc pow chain, then issue the V rcp ----
        float mm   = m * m;
        float mh   = m * h40;
        float pow1 = mm * mh;                            // GNA*m^3*h
        float n2   = n * n;
        float n35  = 35.0f * n2;
        float pow2 = n2 * n35;                           // GK*n^4
        float psum = pow1 + pow2;
        float Gp   = fmaf(0.01f, psum, yG);              // 1 + G
        float r    = rcpf_(Gp);

        // ---- rcp shadow: previous step's output sigmoid + store ----
        float eS   = ex2f_(argS_prev);
        float outP = rcpf_(1.0f + eS);
        *olPrev = outP;
        olPrev += L_DIM;

        // ---- rcp shadow: y-rail (V-independent), series rcp, pY <= 0.011 ----
        float pY = fmaf(0.01f, zc, 0.001f);
        float rY = fmaf(pY, fmaf(pY, 1.0f - pY, -1.0f), 1.0f);
        float yn = fmaf(zc, 0.02f, fmaf(-pY, y, y)) * rY;

        // ---- E / num (parallel with rcp) ----
        float E    = fmaf(pow1, 55.0f, fmaf(pow2, -77.0f, -19.5f));
        float b2   = fmaf(0.02f, E, fmaf(2.0f, V, 0.02f));
        float num  = fmaf(-V, Gp, b2);
        float num9  = num * c9;
        float num12 = num * c12;
        float num01 = num * 0.01f;
        float numS  = num * (-cSIG);

        // ---- consume r: Vn + all ex2 args ----
        float Vn    = num * r;
        float dv25  = fmaf(num,   r, -25.0f);
        float dv35  = fmaf(num,   r,  35.0f);
        float dv01N = fmaf(num01, r, -0.25f);
        float dv01M = fmaf(num01, r,  0.35f);
        float argN  = fmaf(num9,  r, -25.0f * c9);
        float argM  = fmaf(num9,  r,  35.0f * c9);
        float argH  = fmaf(num12, r,  34.0f * c12);
        argS_prev   = fmaf(numS,  r, -20.0f * cSIG);

        float eN = ex2f_(argN);
        float eM = ex2f_(argM);
        float eH = ex2f_(argH);

        // ---- three rails interleaved (independent ~40-cyc chains) ----
        float DN   = eN - 1.0f;
        float DM   = eM - 1.0f;
        float tH2  = eH * eH;
        float setN = fmaf(0.02f,  eN, 0.002f);
        float setM = fmaf(0.182f, eM, 0.124f);
        float qN   = dv01N * setN;
        float qM   = dv01M * setM;
        float wH   = fmaf(-0.0025f, tH2, eH - cAH01);    // t - c - 0.0025 t^2
        float dN   = DN + qN;
        float dM   = DM + qM;
        float denH = fmaf( 0.0025f, tH2, eH + cAH01);    // t + c + 0.0025 t^2
        float rrN  = rcpf_(dN);
        float rrM  = rcpf_(dM);
        float rrH  = rcpf_(denH);
        float scEN = (dv25 * eN) * 4.0e-4f;              // 0.02*0.02
        float scEM = (dv35 * eM) * (0.02f * 0.182f);
        float nmN  = fmaf(n, DN - qN, scEN);
        float nmM  = fmaf(m, DM - qM, scEM);
        float nmH  = fmaf(h, wH, 2.0f * cAH01);
        float resN = nmN * rrN;
        float resM = nmM * rrM;
        float resH = nmH * rrH;

        // reference's exact-equality singularity patches
        n = (dv25 == 0.0f) ? fmaf(n, kNp, cNp) : resN;
        m = (dv35 == 0.0f) ? fmaf(m, kMp, cMp) : resM;
        h = resH;
        y = yn;
        V = Vn;

        // stage off-spine values for next step
        h40 = 40.0f * h;
        yG  = fmaf(0.01f, yn, 1.003f);
    }

    // drain the pipelined output (row N_DIM-1)
    {
        float eS = ex2f_(argS_prev);
        *olPrev = rcpf_(1.0f + eS);
    }
}

extern "C" void kernel_launch(void* const* d_in, const int* in_sizes, int n_in,
                              void* d_out, int out_size) {
    const float* z = (const float*)d_in[0];
    float* out = (float*)d_out;
    hh_synaptic_kernel<<<128, 128>>>(z, out);
}